// round 3
// baseline (speedup 1.0000x reference)
#include <cuda_runtime.h>
#include <cstdint>

typedef unsigned long long ull;

#define BB 1024
#define TT 128
#define DD 13
#define HH 512
#define CC 9
#define BT (BB*TT)
#define EPSF 1e-5f
#define NRB 128            // recurrence CTAs == stats partials

// ---------------- scratch (device globals) ----------------
__device__ float g_xn[BT*16];
__device__ float g_xK[BT*HH];
__device__ float g_z [BT*HH];
__device__ float g_o [BT*HH];
__device__ float g_psum[NRB*HH];
__device__ float g_psq [NRB*HH];
__device__ float g_mean[HH], g_rstd[HH], g_s[HH], g_c[HH];
__device__ ulonglong2 g_Wq [128*HH];   // quad-packed transposed recurrence W
__device__ ulonglong2 g_Wkq[128*HH];   // quad-packed transposed BN-folded WxK2
__device__ ulonglong2 g_Wzq[128*HH];   // quad-packed transposed BN-folded Wxz2
__device__ float g_bk[HH], g_bz[HH];

// ---------------- helpers ----------------
__device__ __forceinline__ ull pk2(float x, float y){
    ull r; asm("mov.b64 %0,{%1,%2};" : "=l"(r) : "f"(x), "f"(y)); return r;
}
__device__ __forceinline__ float2 upk2(ull v){
    float2 f; asm("mov.b64 {%0,%1},%2;" : "=f"(f.x), "=f"(f.y) : "l"(v)); return f;
}
__device__ __forceinline__ void fma2(ull &d, ull a, ull b){
    asm("fma.rn.f32x2 %0,%1,%2,%0;" : "+l"(d) : "l"(a), "l"(b));
}
// ld.shared.v2.u64: two packed fp32 pairs
__device__ __forceinline__ void lds2(ull &a, ull &b, const float* p){
    unsigned sa = (unsigned)__cvta_generic_to_shared(p);
    asm volatile("ld.shared.v2.u64 {%0,%1},[%2];" : "=l"(a), "=l"(b) : "r"(sa));
}
__device__ __forceinline__ float sigm_f(float x){
    return __fdividef(1.f, 1.f + __expf(-x));
}
__device__ __forceinline__ float tanh_f(float x){
    return 1.f - 2.f*__fdividef(1.f, __expf(2.f*x) + 1.f);
}

// ---------------- 1) input LayerNorm over D=13 ----------------
__global__ void k_ln(const float* __restrict__ x, const float* __restrict__ g,
                     const float* __restrict__ b){
    int m = blockIdx.x*blockDim.x + threadIdx.x;
    if (m >= BT) return;
    const float* r = x + m*DD;
    float s = 0.f;
    #pragma unroll
    for (int k=0;k<DD;k++) s += r[k];
    float mu = s * (1.f/DD);
    float v = 0.f;
    #pragma unroll
    for (int k=0;k<DD;k++){ float d = r[k]-mu; v += d*d; }
    float rs = rsqrtf(v*(1.f/DD) + EPSF);
    float* o = g_xn + m*16;
    #pragma unroll
    for (int k=0;k<DD;k++) o[k] = (r[k]-mu)*rs*g[k] + b[k];
    o[13]=0.f; o[14]=0.f; o[15]=0.f;
}

// ---------------- 2) layer-1 projections (K=13), W in registers ----------------
__global__ void __launch_bounds__(512) k_proj1(const float* __restrict__ WK, const float* __restrict__ bK,
                                               const float* __restrict__ WZ, const float* __restrict__ bZ){
    __shared__ float xt[64][16];
    int tid = threadIdx.x;
    int m0  = blockIdx.x*64;
    #pragma unroll
    for (int i=0;i<2;i++){
        int idx = tid + i*512;
        xt[idx>>4][idx&15] = g_xn[m0*16 + idx];
    }
    float wk[DD], wz[DD];
    #pragma unroll
    for (int i=0;i<DD;i++){ wk[i]=WK[tid*DD+i]; wz[i]=WZ[tid*DD+i]; }
    float bk = bK[tid], bz = bZ[tid];
    __syncthreads();
    for (int m=0;m<64;m++){
        float ak = bk, az = bz;
        #pragma unroll
        for (int i=0;i<DD;i++){ float xv = xt[m][i]; ak = fmaf(xv,wk[i],ak); az = fmaf(xv,wz[i],az); }
        g_xK[(m0+m)*HH + tid] = ak;
        g_z [(m0+m)*HH + tid] = tanh_f(az);
    }
}

// ---------------- 3) pack W: [j][k] -> quad-packed transposed [k/4][j] ----------------
__global__ void k_pack(const float* __restrict__ src, int sel, int scaled){
    __shared__ float ts[32][65];
    ulonglong2* dst = (sel==0) ? g_Wq : ((sel==1) ? g_Wkq : g_Wzq);
    int t  = threadIdx.x;            // 256 threads
    int j0 = blockIdx.x*32;
    int k0 = blockIdx.y*64;
    #pragma unroll
    for (int it=0; it<8; it++){
        int idx = it*256 + t;
        int jj = idx >> 6, kk = idx & 63;
        float v = src[(j0+jj)*HH + k0 + kk];
        if (scaled) v *= g_s[k0+kk];
        ts[jj][kk] = v;
    }
    __syncthreads();
    #pragma unroll
    for (int it=0; it<2; it++){
        int idx = it*256 + t;
        int jj = idx & 31, kql = idx >> 5;   // kql 0..15
        ulonglong2 o;
        o.x = pk2(ts[jj][4*kql  ], ts[jj][4*kql+1]);
        o.y = pk2(ts[jj][4*kql+2], ts[jj][4*kql+3]);
        dst[(k0/4 + kql)*HH + j0 + jj] = o;
    }
}

// ---------------- 4) recurrence: 256 thr, 2 outputs/thread, ping-pong h ----------------
__global__ void __launch_bounds__(256,1) k_recur(const float* __restrict__ bh){
    __shared__ __align__(16) float hs[2][8][HH];
    int tid = threadIdx.x;
    int j1  = tid + 256;
    int b0  = blockIdx.x*8;
    #pragma unroll
    for (int r=0;r<8;r++){ hs[0][r][tid]=0.f; hs[0][r][j1]=0.f; }
    float bj0 = bh[tid], bj1 = bh[j1];
    float ss0=0.f, sq0=0.f, ss1=0.f, sq1=0.f;
    __syncthreads();

    int p = 0;
    for (int t=0;t<TT;t++){
        float gk0[8], zt0[8], gk1[8], zt1[8];
        int off[8];
        #pragma unroll
        for (int r=0;r<8;r++){
            off[r] = ((b0+r)*TT + t)*HH;
            gk0[r] = g_xK[off[r]+tid];
            zt0[r] = g_z [off[r]+tid];
            gk1[r] = g_xK[off[r]+j1];
            zt1[r] = g_z [off[r]+j1];
        }
        ull a0[8], a1[8];
        #pragma unroll
        for (int r=0;r<8;r++){ a0[r]=0ull; a1[r]=0ull; }

        const ulonglong2* __restrict__ w0 = g_Wq + tid;
        const ulonglong2* __restrict__ w1 = g_Wq + j1;
        #pragma unroll 2
        for (int kq=0; kq<128; kq++){
            ulonglong2 wa = __ldg(w0 + kq*HH);
            ulonglong2 wb = __ldg(w1 + kq*HH);
            #pragma unroll
            for (int r=0;r<8;r++){
                ull h0,h1;
                lds2(h0,h1,&hs[p][r][4*kq]);
                fma2(a0[r],h0,wa.x); fma2(a0[r],h1,wa.y);
                fma2(a1[r],h0,wb.x); fma2(a1[r],h1,wb.y);
            }
        }
        #pragma unroll
        for (int r=0;r<8;r++){
            float2 A = upk2(a0[r]);
            float2 Bv= upk2(a1[r]);
            float K0 = sigm_f(gk0[r] + A.x + A.y + bj0);
            float K1 = sigm_f(gk1[r] + Bv.x+ Bv.y+ bj1);
            float h00 = hs[p][r][tid], h01 = hs[p][r][j1];
            float n0 = tanh_f(K0*h00 + (1.f-K0)*zt0[r]);
            float n1 = tanh_f(K1*h01 + (1.f-K1)*zt1[r]);
            hs[1-p][r][tid] = n0;
            hs[1-p][r][j1]  = n1;
            g_o[off[r]+tid] = n0;
            g_o[off[r]+j1]  = n1;
            ss0 += n0; sq0 = fmaf(n0,n0,sq0);
            ss1 += n1; sq1 = fmaf(n1,n1,sq1);
        }
        __syncthreads();
        p ^= 1;
    }
    g_psum[blockIdx.x*HH + tid] = ss0;
    g_psum[blockIdx.x*HH + j1 ] = ss1;
    g_psq [blockIdx.x*HH + tid] = sq0;
    g_psq [blockIdx.x*HH + j1 ] = sq1;
}

// ---------------- 5) finalize BN stats + fold vectors ----------------
__global__ void k_statsfin(const float* __restrict__ bng, const float* __restrict__ bnb){
    int t = threadIdx.x;
    float s = 0.f, q = 0.f;
    for (int i=0;i<NRB;i++){ s += g_psum[i*HH + t]; q += g_psq[i*HH + t]; }
    float m  = s * (1.f/BT);
    float v  = q * (1.f/BT) - m*m;
    float rs = rsqrtf(v + EPSF);
    g_mean[t] = m;
    g_rstd[t] = rs;
    float sc = bng[t]*rs;
    g_s[t] = sc;
    g_c[t] = bnb[t] - m*sc;
}

// ---------------- 6) folded biases: b' = b + W @ c ----------------
__global__ void k_bias(const float* __restrict__ WK, const float* __restrict__ bK,
                       const float* __restrict__ WZ, const float* __restrict__ bZ){
    __shared__ float sk[8], sz[8];
    int j = blockIdx.x, t = threadIdx.x;     // 256 threads
    float ck = 0.f, cz = 0.f;
    for (int k=t;k<HH;k+=256){
        float c = g_c[k];
        ck = fmaf(WK[j*HH+k], c, ck);
        cz = fmaf(WZ[j*HH+k], c, cz);
    }
    #pragma unroll
    for (int o=16;o;o>>=1){ ck += __shfl_xor_sync(~0u,ck,o); cz += __shfl_xor_sync(~0u,cz,o); }
    if ((t&31)==0){ sk[t>>5]=ck; sz[t>>5]=cz; }
    __syncthreads();
    if (t==0){
        float a=0.f,b2=0.f;
        #pragma unroll
        for (int i=0;i<8;i++){ a+=sk[i]; b2+=sz[i]; }
        g_bk[j] = bK[j] + a;
        g_bz[j] = bZ[j] + b2;
    }
}

// ---------------- 7) fused layer-2/3 projections: 256 thr, 2 outs, 16 rows ----------------
__global__ void __launch_bounds__(256,1) k_proj2(){
    __shared__ __align__(16) float xs[16*HH];   // 32 KB
    int tid = threadIdx.x;
    int j1  = tid + 256;
    int m0  = blockIdx.x*16;
    const float4* __restrict__ src = (const float4*)(g_o + (size_t)m0*HH);
    float4* d4 = (float4*)xs;
    #pragma unroll
    for (int i=0;i<8;i++) d4[tid + i*256] = src[tid + i*256];
    __syncthreads();

    ull aK0[16], aK1[16], aZ0[16], aZ1[16];
    #pragma unroll
    for (int r=0;r<16;r++){ aK0[r]=0ull; aK1[r]=0ull; aZ0[r]=0ull; aZ1[r]=0ull; }

    const ulonglong2* __restrict__ wk0 = g_Wkq + tid;
    const ulonglong2* __restrict__ wk1 = g_Wkq + j1;
    const ulonglong2* __restrict__ wz0 = g_Wzq + tid;
    const ulonglong2* __restrict__ wz1 = g_Wzq + j1;
    #pragma unroll 1
    for (int kq=0; kq<128; kq++){
        ulonglong2 ka = __ldg(wk0 + kq*HH);
        ulonglong2 kb = __ldg(wk1 + kq*HH);
        ulonglong2 za = __ldg(wz0 + kq*HH);
        ulonglong2 zb = __ldg(wz1 + kq*HH);
        #pragma unroll
        for (int r=0;r<16;r++){
            ull h0,h1;
            lds2(h0,h1,&xs[r*HH + 4*kq]);
            fma2(aK0[r],h0,ka.x); fma2(aK0[r],h1,ka.y);
            fma2(aK1[r],h0,kb.x); fma2(aK1[r],h1,kb.y);
            fma2(aZ0[r],h0,za.x); fma2(aZ0[r],h1,za.y);
            fma2(aZ1[r],h0,zb.x); fma2(aZ1[r],h1,zb.y);
        }
    }
    float bk0 = g_bk[tid], bk1 = g_bk[j1];
    float bz0 = g_bz[tid], bz1 = g_bz[j1];
    #pragma unroll
    for (int r=0;r<16;r++){
        float2 a = upk2(aK0[r]);
        g_xK[(m0+r)*HH + tid] = a.x + a.y + bk0;
        float2 b = upk2(aK1[r]);
        g_xK[(m0+r)*HH + j1 ] = b.x + b.y + bk1;
        float2 c = upk2(aZ0[r]);
        g_z [(m0+r)*HH + tid] = tanh_f(c.x + c.y + bz0);
        float2 d = upk2(aZ1[r]);
        g_z [(m0+r)*HH + j1 ] = tanh_f(d.x + d.y + bz1);
    }
}

// ---------------- 8) head: BN + LN(last step) + logits + log_softmax ----------------
__global__ void __launch_bounds__(512) k_head(const float* __restrict__ bng, const float* __restrict__ bnb,
                                              const float* __restrict__ lng, const float* __restrict__ lnb,
                                              const float* __restrict__ Wc,  const float* __restrict__ bc,
                                              float* __restrict__ out){
    __shared__ float red[16];
    __shared__ float hsm[HH];
    __shared__ float lg[CC];
    int b = blockIdx.x, tid = threadIdx.x;

    float v = g_o[(b*TT + TT-1)*HH + tid];
    float y = (v - g_mean[tid])*g_rstd[tid]*bng[tid] + bnb[tid];

    float t1 = y;
    #pragma unroll
    for (int o=16;o;o>>=1) t1 += __shfl_xor_sync(~0u,t1,o);
    if ((tid&31)==0) red[tid>>5] = t1;
    __syncthreads();
    float mu = 0.f;
    #pragma unroll
    for (int i=0;i<16;i++) mu += red[i];
    mu *= (1.f/HH);
    __syncthreads();

    float d = y - mu;
    float t2 = d*d;
    #pragma unroll
    for (int o=16;o;o>>=1) t2 += __shfl_xor_sync(~0u,t2,o);
    if ((tid&31)==0) red[tid>>5] = t2;
    __syncthreads();
    float var = 0.f;
    #pragma unroll
    for (int i=0;i<16;i++) var += red[i];
    var *= (1.f/HH);
    float rs = rsqrtf(var + EPSF);
    hsm[tid] = d*rs*lng[tid] + lnb[tid];
    __syncthreads();

    int w = tid>>5, l = tid&31;
    if (w < CC){
        float p = 0.f;
        for (int k=l;k<HH;k+=32) p = fmaf(hsm[k], Wc[w*HH + k], p);
        #pragma unroll
        for (int o=16;o;o>>=1) p += __shfl_xor_sync(~0u,p,o);
        if (l==0) lg[w] = p + bc[w];
    }
    __syncthreads();
    if (tid==0){
        float mx = lg[0];
        #pragma unroll
        for (int c=1;c<CC;c++) mx = fmaxf(mx, lg[c]);
        float sm = 0.f;
        #pragma unroll
        for (int c=0;c<CC;c++) sm += expf(lg[c]-mx);
        float lse = mx + logf(sm);
        #pragma unroll
        for (int c=0;c<CC;c++) out[b*CC + c] = lg[c] - lse;
    }
}

// ---------------- launch sequence ----------------
extern "C" void kernel_launch(void* const* d_in, const int* in_sizes, int n_in,
                              void* d_out, int out_size){
    const float* x      = (const float*)d_in[0];
    const float* inln_g = (const float*)d_in[1];
    const float* inln_b = (const float*)d_in[2];
    const float* WxK1   = (const float*)d_in[3];
    const float* bxK1   = (const float*)d_in[4];
    const float* Wxz1   = (const float*)d_in[5];
    const float* bxz1   = (const float*)d_in[6];
    const float* WhK1   = (const float*)d_in[7];
    const float* bhK1   = (const float*)d_in[8];
    const float* bn1_g  = (const float*)d_in[9];
    const float* bn1_b  = (const float*)d_in[10];
    const float* WxK2   = (const float*)d_in[11];
    const float* bxK2   = (const float*)d_in[12];
    const float* Wxz2   = (const float*)d_in[13];
    const float* bxz2   = (const float*)d_in[14];
    const float* WhK2   = (const float*)d_in[15];
    const float* bhK2   = (const float*)d_in[16];
    const float* bn2_g  = (const float*)d_in[17];
    const float* bn2_b  = (const float*)d_in[18];
    const float* cln_g  = (const float*)d_in[19];
    const float* cln_b  = (const float*)d_in[20];
    const float* Wc     = (const float*)d_in[21];
    const float* bc     = (const float*)d_in[22];
    float* out = (float*)d_out;

    dim3 pg(16,8);

    // input LN + layer-1 projections
    k_ln   <<<BT/256, 256>>>(x, inln_g, inln_b);
    k_proj1<<<BT/64, 512>>>(WxK1, bxK1, Wxz1, bxz1);

    // layer 1
    k_pack   <<<pg, 256>>>(WhK1, 0, 0);
    k_recur  <<<NRB, 256>>>(bhK1);
    k_statsfin<<<1, 512>>>(bn1_g, bn1_b);
    k_pack   <<<pg, 256>>>(WxK2, 1, 1);
    k_pack   <<<pg, 256>>>(Wxz2, 2, 1);
    k_bias   <<<HH, 256>>>(WxK2, bxK2, Wxz2, bxz2);

    // layer 2
    k_proj2  <<<BT/16, 256>>>();
    k_pack   <<<pg, 256>>>(WhK2, 0, 0);
    k_recur  <<<NRB, 256>>>(bhK2);
    k_statsfin<<<1, 512>>>(bn2_g, bn2_b);
    k_pack   <<<pg, 256>>>(WxK2, 1, 1);
    k_pack   <<<pg, 256>>>(Wxz2, 2, 1);
    k_bias   <<<HH, 256>>>(WxK2, bxK2, Wxz2, bxz2);

    // layer 3 (shared weights; g_Wq still holds packed WhK2)
    k_proj2  <<<BT/16, 256>>>();
    k_recur  <<<NRB, 256>>>(bhK2);
    k_statsfin<<<1, 512>>>(bn2_g, bn2_b);

    // head
    k_head <<<BB, 512>>>(bn2_g, bn2_b, cln_g, cln_b, Wc, bc, out);
}

// round 4
// speedup vs baseline: 1.1907x; 1.1907x over previous
#include <cuda_runtime.h>
#include <cstdint>

typedef unsigned long long ull;

#define BB 1024
#define TT 128
#define DD 13
#define HH 512
#define CC 9
#define BT (BB*TT)
#define EPSF 1e-5f
#define NRB 128

// ---------------- scratch (device globals) ----------------
__device__ float g_xn[BT*16];
__device__ float g_xK[BT*HH];
__device__ float g_z [BT*HH];
__device__ float g_o [BT*HH];
__device__ float g_psum[NRB*HH];
__device__ float g_psq [NRB*HH];
__device__ float g_mean[HH], g_rstd[HH], g_s[HH], g_c[HH];
__device__ ulonglong2 g_Wq [128*HH];
__device__ ulonglong2 g_Wkq[128*HH];
__device__ ulonglong2 g_Wzq[128*HH];
__device__ float g_bk[HH], g_bz[HH];

// ---------------- helpers ----------------
__device__ __forceinline__ ull pk2(float x, float y){
    ull r; asm("mov.b64 %0,{%1,%2};" : "=l"(r) : "f"(x), "f"(y)); return r;
}
__device__ __forceinline__ float2 upk2(ull v){
    float2 f; asm("mov.b64 {%0,%1},%2;" : "=f"(f.x), "=f"(f.y) : "l"(v)); return f;
}
__device__ __forceinline__ void fma2(ull &d, ull a, ull b){
    asm("fma.rn.f32x2 %0,%1,%2,%0;" : "+l"(d) : "l"(a), "l"(b));
}
__device__ __forceinline__ void lds2(ull &a, ull &b, const float* p){
    unsigned sa = (unsigned)__cvta_generic_to_shared(p);
    asm volatile("ld.shared.v2.u64 {%0,%1},[%2];" : "=l"(a), "=l"(b) : "r"(sa));
}
__device__ __forceinline__ float sigm_f(float x){
    return __fdividef(1.f, 1.f + __expf(-x));
}
__device__ __forceinline__ float tanh_f(float x){
    return 1.f - 2.f*__fdividef(1.f, __expf(2.f*x) + 1.f);
}

// ---------------- 1) input LayerNorm over D=13 ----------------
__global__ void k_ln(const float* __restrict__ x, const float* __restrict__ g,
                     const float* __restrict__ b){
    int m = blockIdx.x*blockDim.x + threadIdx.x;
    if (m >= BT) return;
    const float* r = x + m*DD;
    float s = 0.f;
    #pragma unroll
    for (int k=0;k<DD;k++) s += r[k];
    float mu = s * (1.f/DD);
    float v = 0.f;
    #pragma unroll
    for (int k=0;k<DD;k++){ float d = r[k]-mu; v += d*d; }
    float rs = rsqrtf(v*(1.f/DD) + EPSF);
    float* o = g_xn + m*16;
    #pragma unroll
    for (int k=0;k<DD;k++) o[k] = (r[k]-mu)*rs*g[k] + b[k];
    o[13]=0.f; o[14]=0.f; o[15]=0.f;
}

// ---------------- 2) layer-1 projections (K=13) ----------------
__global__ void __launch_bounds__(512) k_proj1(const float* __restrict__ WK, const float* __restrict__ bK,
                                               const float* __restrict__ WZ, const float* __restrict__ bZ){
    __shared__ float xt[64][16];
    int tid = threadIdx.x;
    int m0  = blockIdx.x*64;
    #pragma unroll
    for (int i=0;i<2;i++){
        int idx = tid + i*512;
        xt[idx>>4][idx&15] = g_xn[m0*16 + idx];
    }
    float wk[DD], wz[DD];
    #pragma unroll
    for (int i=0;i<DD;i++){ wk[i]=WK[tid*DD+i]; wz[i]=WZ[tid*DD+i]; }
    float bk = bK[tid], bz = bZ[tid];
    __syncthreads();
    for (int m=0;m<64;m++){
        float ak = bk, az = bz;
        #pragma unroll
        for (int i=0;i<DD;i++){ float xv = xt[m][i]; ak = fmaf(xv,wk[i],ak); az = fmaf(xv,wz[i],az); }
        g_xK[(m0+m)*HH + tid] = ak;
        g_z [(m0+m)*HH + tid] = tanh_f(az);
    }
}

// ---------------- 3) pack W: [j][k] -> quad-packed transposed [k/4][j] ----------------
__global__ void k_pack(const float* __restrict__ src, int sel, int scaled){
    __shared__ float ts[32][65];
    ulonglong2* dst = (sel==0) ? g_Wq : ((sel==1) ? g_Wkq : g_Wzq);
    int t  = threadIdx.x;            // 256 threads
    int j0 = blockIdx.x*32;
    int k0 = blockIdx.y*64;
    #pragma unroll
    for (int it=0; it<8; it++){
        int idx = it*256 + t;
        int jj = idx >> 6, kk = idx & 63;
        float v = src[(j0+jj)*HH + k0 + kk];
        if (scaled) v *= g_s[k0+kk];
        ts[jj][kk] = v;
    }
    __syncthreads();
    #pragma unroll
    for (int it=0; it<2; it++){
        int idx = it*256 + t;
        int jj = idx & 31, kql = idx >> 5;
        ulonglong2 o;
        o.x = pk2(ts[jj][4*kql  ], ts[jj][4*kql+1]);
        o.y = pk2(ts[jj][4*kql+2], ts[jj][4*kql+3]);
        dst[(k0/4 + kql)*HH + j0 + jj] = o;
    }
}

// ---------------- 4) recurrence: 2 outs/thread, prefetch-pipelined W ----------------
__global__ void __launch_bounds__(256,1) k_recur(const float* __restrict__ bh){
    __shared__ __align__(16) float hs[2][8][HH];
    int tid = threadIdx.x;
    int j1  = tid + 256;
    int b0  = blockIdx.x*8;
    #pragma unroll
    for (int r=0;r<8;r++){ hs[0][r][tid]=0.f; hs[0][r][j1]=0.f; }
    float bj0 = bh[tid], bj1 = bh[j1];
    float ss0=0.f, sq0=0.f, ss1=0.f, sq1=0.f;
    __syncthreads();

    const ulonglong2* __restrict__ w0 = g_Wq + tid;
    const ulonglong2* __restrict__ w1 = g_Wq + j1;

    int p = 0;
    for (int t=0;t<TT;t++){
        float gk0[8], zt0[8], gk1[8], zt1[8];
        int off[8];
        #pragma unroll
        for (int r=0;r<8;r++){
            off[r] = ((b0+r)*TT + t)*HH;
            gk0[r] = g_xK[off[r]+tid];
            zt0[r] = g_z [off[r]+tid];
            gk1[r] = g_xK[off[r]+j1];
            zt1[r] = g_z [off[r]+j1];
        }
        ull a0[8], a1[8];
        #pragma unroll
        for (int r=0;r<8;r++){ a0[r]=0ull; a1[r]=0ull; }

        const float* hb = &hs[p][0][0];

        // software pipeline: prefetch distance = 4 kq
        ulonglong2 A[4], B[4];
        #pragma unroll
        for (int i=0;i<4;i++){ A[i] = __ldg(w0 + i*HH); B[i] = __ldg(w1 + i*HH); }

        #pragma unroll 1
        for (int kq=0; kq<128; kq+=4){
            int nq = (kq+4) & 127;
            ulonglong2 An[4], Bn[4];
            #pragma unroll
            for (int i=0;i<4;i++){ An[i] = __ldg(w0 + (nq+i)*HH); Bn[i] = __ldg(w1 + (nq+i)*HH); }
            #pragma unroll
            for (int u=0;u<4;u++){
                #pragma unroll
                for (int r=0;r<8;r++){
                    ull h0,h1;
                    lds2(h0,h1, hb + r*HH + 4*(kq+u));
                    fma2(a0[r],h0,A[u].x); fma2(a0[r],h1,A[u].y);
                    fma2(a1[r],h0,B[u].x); fma2(a1[r],h1,B[u].y);
                }
            }
            #pragma unroll
            for (int i=0;i<4;i++){ A[i]=An[i]; B[i]=Bn[i]; }
        }
        #pragma unroll
        for (int r=0;r<8;r++){
            float2 Av = upk2(a0[r]);
            float2 Bv = upk2(a1[r]);
            float K0 = sigm_f(gk0[r] + Av.x + Av.y + bj0);
            float K1 = sigm_f(gk1[r] + Bv.x + Bv.y + bj1);
            float h00 = hs[p][r][tid], h01 = hs[p][r][j1];
            float n0 = tanh_f(K0*h00 + (1.f-K0)*zt0[r]);
            float n1 = tanh_f(K1*h01 + (1.f-K1)*zt1[r]);
            hs[1-p][r][tid] = n0;
            hs[1-p][r][j1]  = n1;
            g_o[off[r]+tid] = n0;
            g_o[off[r]+j1]  = n1;
            ss0 += n0; sq0 = fmaf(n0,n0,sq0);
            ss1 += n1; sq1 = fmaf(n1,n1,sq1);
        }
        __syncthreads();
        p ^= 1;
    }
    g_psum[blockIdx.x*HH + tid] = ss0;
    g_psum[blockIdx.x*HH + j1 ] = ss1;
    g_psq [blockIdx.x*HH + tid] = sq0;
    g_psq [blockIdx.x*HH + j1 ] = sq1;
}

// ---------------- 5) finalize BN stats + fold vectors ----------------
__global__ void k_statsfin(const float* __restrict__ bng, const float* __restrict__ bnb){
    int t = threadIdx.x;
    float s = 0.f, q = 0.f;
    for (int i=0;i<NRB;i++){ s += g_psum[i*HH + t]; q += g_psq[i*HH + t]; }
    float m  = s * (1.f/BT);
    float v  = q * (1.f/BT) - m*m;
    float rs = rsqrtf(v + EPSF);
    g_mean[t] = m;
    g_rstd[t] = rs;
    float sc = bng[t]*rs;
    g_s[t] = sc;
    g_c[t] = bnb[t] - m*sc;
}

// ---------------- 6) folded biases: b' = b + W @ c ----------------
__global__ void k_bias(const float* __restrict__ WK, const float* __restrict__ bK,
                       const float* __restrict__ WZ, const float* __restrict__ bZ){
    __shared__ float sk[8], sz[8];
    int j = blockIdx.x, t = threadIdx.x;
    float ck = 0.f, cz = 0.f;
    for (int k=t;k<HH;k+=256){
        float c = g_c[k];
        ck = fmaf(WK[j*HH+k], c, ck);
        cz = fmaf(WZ[j*HH+k], c, cz);
    }
    #pragma unroll
    for (int o=16;o;o>>=1){ ck += __shfl_xor_sync(~0u,ck,o); cz += __shfl_xor_sync(~0u,cz,o); }
    if ((t&31)==0){ sk[t>>5]=ck; sz[t>>5]=cz; }
    __syncthreads();
    if (t==0){
        float a=0.f,b2=0.f;
        #pragma unroll
        for (int i=0;i<8;i++){ a+=sk[i]; b2+=sz[i]; }
        g_bk[j] = bK[j] + a;
        g_bz[j] = bZ[j] + b2;
    }
}

// ---------------- 7) layer-2/3 projections: one matrix per kernel, 2 CTAs/SM ----------------
template<int ZP>
__global__ void __launch_bounds__(256,2) k_proj2(){
    __shared__ __align__(16) float xs[16*HH];   // 32 KB
    int tid = threadIdx.x;
    int j1  = tid + 256;
    int m0  = blockIdx.x*16;
    const float4* __restrict__ src = (const float4*)(g_o + (size_t)m0*HH);
    float4* d4 = (float4*)xs;
    #pragma unroll
    for (int i=0;i<8;i++) d4[tid + i*256] = src[tid + i*256];
    __syncthreads();

    ull a0[16], a1[16];
    #pragma unroll
    for (int r=0;r<16;r++){ a0[r]=0ull; a1[r]=0ull; }

    const ulonglong2* __restrict__ Wb = ZP ? g_Wzq : g_Wkq;
    const ulonglong2* __restrict__ w0 = Wb + tid;
    const ulonglong2* __restrict__ w1 = Wb + j1;

    // prefetch distance 4
    ulonglong2 A[4], B[4];
    #pragma unroll
    for (int i=0;i<4;i++){ A[i] = __ldg(w0 + i*HH); B[i] = __ldg(w1 + i*HH); }

    #pragma unroll 1
    for (int kq=0; kq<128; kq+=4){
        int nq = (kq+4) & 127;
        ulonglong2 An[4], Bn[4];
        #pragma unroll
        for (int i=0;i<4;i++){ An[i] = __ldg(w0 + (nq+i)*HH); Bn[i] = __ldg(w1 + (nq+i)*HH); }
        #pragma unroll
        for (int u=0;u<4;u++){
            #pragma unroll
            for (int r=0;r<16;r++){
                ull h0,h1;
                lds2(h0,h1,&xs[r*HH + 4*(kq+u)]);
                fma2(a0[r],h0,A[u].x); fma2(a0[r],h1,A[u].y);
                fma2(a1[r],h0,B[u].x); fma2(a1[r],h1,B[u].y);
            }
        }
        #pragma unroll
        for (int i=0;i<4;i++){ A[i]=An[i]; B[i]=Bn[i]; }
    }

    if (ZP){
        float b0v = g_bz[tid], b1v = g_bz[j1];
        #pragma unroll
        for (int r=0;r<16;r++){
            float2 a = upk2(a0[r]);
            g_z[(m0+r)*HH + tid] = tanh_f(a.x + a.y + b0v);
            float2 b = upk2(a1[r]);
            g_z[(m0+r)*HH + j1 ] = tanh_f(b.x + b.y + b1v);
        }
    } else {
        float b0v = g_bk[tid], b1v = g_bk[j1];
        #pragma unroll
        for (int r=0;r<16;r++){
            float2 a = upk2(a0[r]);
            g_xK[(m0+r)*HH + tid] = a.x + a.y + b0v;
            float2 b = upk2(a1[r]);
            g_xK[(m0+r)*HH + j1 ] = b.x + b.y + b1v;
        }
    }
}

// ---------------- 8) head ----------------
__global__ void __launch_bounds__(512) k_head(const float* __restrict__ bng, const float* __restrict__ bnb,
                                              const float* __restrict__ lng, const float* __restrict__ lnb,
                                              const float* __restrict__ Wc,  const float* __restrict__ bc,
                                              float* __restrict__ out){
    __shared__ float red[16];
    __shared__ float hsm[HH];
    __shared__ float lg[CC];
    int b = blockIdx.x, tid = threadIdx.x;

    float v = g_o[(b*TT + TT-1)*HH + tid];
    float y = (v - g_mean[tid])*g_rstd[tid]*bng[tid] + bnb[tid];

    float t1 = y;
    #pragma unroll
    for (int o=16;o;o>>=1) t1 += __shfl_xor_sync(~0u,t1,o);
    if ((tid&31)==0) red[tid>>5] = t1;
    __syncthreads();
    float mu = 0.f;
    #pragma unroll
    for (int i=0;i<16;i++) mu += red[i];
    mu *= (1.f/HH);
    __syncthreads();

    float d = y - mu;
    float t2 = d*d;
    #pragma unroll
    for (int o=16;o;o>>=1) t2 += __shfl_xor_sync(~0u,t2,o);
    if ((tid&31)==0) red[tid>>5] = t2;
    __syncthreads();
    float var = 0.f;
    #pragma unroll
    for (int i=0;i<16;i++) var += red[i];
    var *= (1.f/HH);
    float rs = rsqrtf(var + EPSF);
    hsm[tid] = d*rs*lng[tid] + lnb[tid];
    __syncthreads();

    int w = tid>>5, l = tid&31;
    if (w < CC){
        float p = 0.f;
        for (int k=l;k<HH;k+=32) p = fmaf(hsm[k], Wc[w*HH + k], p);
        #pragma unroll
        for (int o=16;o;o>>=1) p += __shfl_xor_sync(~0u,p,o);
        if (l==0) lg[w] = p + bc[w];
    }
    __syncthreads();
    if (tid==0){
        float mx = lg[0];
        #pragma unroll
        for (int c=1;c<CC;c++) mx = fmaxf(mx, lg[c]);
        float sm = 0.f;
        #pragma unroll
        for (int c=0;c<CC;c++) sm += expf(lg[c]-mx);
        float lse = mx + logf(sm);
        #pragma unroll
        for (int c=0;c<CC;c++) out[b*CC + c] = lg[c] - lse;
    }
}

// ---------------- launch sequence ----------------
extern "C" void kernel_launch(void* const* d_in, const int* in_sizes, int n_in,
                              void* d_out, int out_size){
    const float* x      = (const float*)d_in[0];
    const float* inln_g = (const float*)d_in[1];
    const float* inln_b = (const float*)d_in[2];
    const float* WxK1   = (const float*)d_in[3];
    const float* bxK1   = (const float*)d_in[4];
    const float* Wxz1   = (const float*)d_in[5];
    const float* bxz1   = (const float*)d_in[6];
    const float* WhK1   = (const float*)d_in[7];
    const float* bhK1   = (const float*)d_in[8];
    const float* bn1_g  = (const float*)d_in[9];
    const float* bn1_b  = (const float*)d_in[10];
    const float* WxK2   = (const float*)d_in[11];
    const float* bxK2   = (const float*)d_in[12];
    const float* Wxz2   = (const float*)d_in[13];
    const float* bxz2   = (const float*)d_in[14];
    const float* WhK2   = (const float*)d_in[15];
    const float* bhK2   = (const float*)d_in[16];
    const float* bn2_g  = (const float*)d_in[17];
    const float* bn2_b  = (const float*)d_in[18];
    const float* cln_g  = (const float*)d_in[19];
    const float* cln_b  = (const float*)d_in[20];
    const float* Wc     = (const float*)d_in[21];
    const float* bc     = (const float*)d_in[22];
    float* out = (float*)d_out;

    dim3 pg(16,8);

    // input LN + layer-1 projections
    k_ln   <<<BT/256, 256>>>(x, inln_g, inln_b);
    k_proj1<<<BT/64, 512>>>(WxK1, bxK1, Wxz1, bxz1);

    // layer 1
    k_pack   <<<pg, 256>>>(WhK1, 0, 0);
    k_recur  <<<NRB, 256>>>(bhK1);
    k_statsfin<<<1, 512>>>(bn1_g, bn1_b);
    k_pack   <<<pg, 256>>>(WxK2, 1, 1);
    k_pack   <<<pg, 256>>>(Wxz2, 2, 1);
    k_bias   <<<HH, 256>>>(WxK2, bxK2, Wxz2, bxz2);

    // layer 2
    k_proj2<0><<<BT/16, 256>>>();
    k_proj2<1><<<BT/16, 256>>>();
    k_pack   <<<pg, 256>>>(WhK2, 0, 0);
    k_recur  <<<NRB, 256>>>(bhK2);
    k_statsfin<<<1, 512>>>(bn2_g, bn2_b);
    k_pack   <<<pg, 256>>>(WxK2, 1, 1);
    k_pack   <<<pg, 256>>>(Wxz2, 2, 1);
    k_bias   <<<HH, 256>>>(WxK2, bxK2, Wxz2, bxz2);

    // layer 3 (shared weights; g_Wq still holds packed WhK2)
    k_proj2<0><<<BT/16, 256>>>();
    k_proj2<1><<<BT/16, 256>>>();
    k_recur  <<<NRB, 256>>>(bhK2);
    k_statsfin<<<1, 512>>>(bn2_g, bn2_b);

    // head
    k_head <<<BB, 512>>>(bn2_g, bn2_b, cln_g, cln_b, Wc, bc, out);
}

// round 5
// speedup vs baseline: 1.3719x; 1.1522x over previous
#include <cuda_runtime.h>
#include <cstdint>

typedef unsigned long long ull;

#define BB 1024
#define TT 128
#define DD 13
#define HH 512
#define CC 9
#define BT (BB*TT)
#define EPSF 1e-5f
#define NRB 128

#define PM 128
#define PN 256
#define PK 32
#define APAD 36
#define BPAD 260
#define PMMA_SMEM ((2*PM*APAD + 2*PK*BPAD)*4)

// ---------------- scratch (device globals) ----------------
__device__ float g_xn[BT*16];
__device__ float g_xK[BT*HH];
__device__ float g_z [BT*HH];
__device__ float g_o [BT*HH];
__device__ float g_psum[NRB*HH];
__device__ float g_psq [NRB*HH];
__device__ float g_mean[HH], g_rstd[HH], g_s[HH], g_c[HH];
__device__ ulonglong2 g_Wq[128*HH];          // quad-packed transposed recurrence W
__device__ float g_Bt[512*1024];             // tf32-rounded, BN-folded [Wk'|Wz'] as [k][n]
__device__ float g_bk[HH], g_bz[HH];
__device__ float g_bcat[1024];

// ---------------- helpers ----------------
__device__ __forceinline__ ull pk2(float x, float y){
    ull r; asm("mov.b64 %0,{%1,%2};" : "=l"(r) : "f"(x), "f"(y)); return r;
}
__device__ __forceinline__ float2 upk2(ull v){
    float2 f; asm("mov.b64 {%0,%1},%2;" : "=f"(f.x), "=f"(f.y) : "l"(v)); return f;
}
__device__ __forceinline__ void fma2(ull &d, ull a, ull b){
    asm("fma.rn.f32x2 %0,%1,%2,%0;" : "+l"(d) : "l"(a), "l"(b));
}
__device__ __forceinline__ void lds2(ull &a, ull &b, const float* p){
    unsigned sa = (unsigned)__cvta_generic_to_shared(p);
    asm volatile("ld.shared.v2.u64 {%0,%1},[%2];" : "=l"(a), "=l"(b) : "r"(sa));
}
__device__ __forceinline__ float sigm_f(float x){
    return __fdividef(1.f, 1.f + __expf(-x));
}
__device__ __forceinline__ float tanh_f(float x){
    return 1.f - 2.f*__fdividef(1.f, __expf(2.f*x) + 1.f);
}
__device__ __forceinline__ uint32_t cvt_tf32(float f){
    uint32_t u; asm("cvt.rna.tf32.f32 %0,%1;" : "=r"(u) : "f"(f)); return u;
}
__device__ __forceinline__ void cp16(uint32_t dst, const void* src){
    asm volatile("cp.async.ca.shared.global [%0],[%1],16;" :: "r"(dst), "l"(src));
}
__device__ __forceinline__ void mma_tf32(float* c, const uint32_t* a, const uint32_t* b){
    asm volatile("mma.sync.aligned.m16n8k8.row.col.f32.tf32.tf32.f32 "
        "{%0,%1,%2,%3},{%4,%5,%6,%7},{%8,%9},{%0,%1,%2,%3};"
        : "+f"(c[0]), "+f"(c[1]), "+f"(c[2]), "+f"(c[3])
        : "r"(a[0]), "r"(a[1]), "r"(a[2]), "r"(a[3]), "r"(b[0]), "r"(b[1]));
}

// ---------------- 1) input LayerNorm over D=13 ----------------
__global__ void k_ln(const float* __restrict__ x, const float* __restrict__ g,
                     const float* __restrict__ b){
    int m = blockIdx.x*blockDim.x + threadIdx.x;
    if (m >= BT) return;
    const float* r = x + m*DD;
    float s = 0.f;
    #pragma unroll
    for (int k=0;k<DD;k++) s += r[k];
    float mu = s * (1.f/DD);
    float v = 0.f;
    #pragma unroll
    for (int k=0;k<DD;k++){ float d = r[k]-mu; v += d*d; }
    float rs = rsqrtf(v*(1.f/DD) + EPSF);
    float* o = g_xn + m*16;
    #pragma unroll
    for (int k=0;k<DD;k++) o[k] = (r[k]-mu)*rs*g[k] + b[k];
    o[13]=0.f; o[14]=0.f; o[15]=0.f;
}

// ---------------- 2) layer-1 projections (K=13) ----------------
__global__ void __launch_bounds__(512) k_proj1(const float* __restrict__ WK, const float* __restrict__ bK,
                                               const float* __restrict__ WZ, const float* __restrict__ bZ){
    __shared__ float xt[64][16];
    int tid = threadIdx.x;
    int m0  = blockIdx.x*64;
    #pragma unroll
    for (int i=0;i<2;i++){
        int idx = tid + i*512;
        xt[idx>>4][idx&15] = g_xn[m0*16 + idx];
    }
    float wk[DD], wz[DD];
    #pragma unroll
    for (int i=0;i<DD;i++){ wk[i]=WK[tid*DD+i]; wz[i]=WZ[tid*DD+i]; }
    float bk = bK[tid], bz = bZ[tid];
    __syncthreads();
    for (int m=0;m<64;m++){
        float ak = bk, az = bz;
        #pragma unroll
        for (int i=0;i<DD;i++){ float xv = xt[m][i]; ak = fmaf(xv,wk[i],ak); az = fmaf(xv,wz[i],az); }
        g_xK[(m0+m)*HH + tid] = ak;
        g_z [(m0+m)*HH + tid] = tanh_f(az);
    }
}

// ---------------- 3) pack recurrence W: [j][k] -> quad-packed transposed [k/4][j] ----------------
__global__ void k_pack(const float* __restrict__ src){
    __shared__ float ts[32][65];
    int t  = threadIdx.x;            // 256 threads
    int j0 = blockIdx.x*32;
    int k0 = blockIdx.y*64;
    #pragma unroll
    for (int it=0; it<8; it++){
        int idx = it*256 + t;
        int jj = idx >> 6, kk = idx & 63;
        ts[jj][kk] = src[(j0+jj)*HH + k0 + kk];
    }
    __syncthreads();
    #pragma unroll
    for (int it=0; it<2; it++){
        int idx = it*256 + t;
        int jj = idx & 31, kql = idx >> 5;
        ulonglong2 o;
        o.x = pk2(ts[jj][4*kql  ], ts[jj][4*kql+1]);
        o.y = pk2(ts[jj][4*kql+2], ts[jj][4*kql+3]);
        g_Wq[(k0/4 + kql)*HH + j0 + jj] = o;
    }
}

// ---------------- 4) recurrence: 512 thr, 1 out/thread, prefetch-pipelined W ----------------
__global__ void __launch_bounds__(512,1) k_recur(const float* __restrict__ bh){
    __shared__ __align__(16) float hs[2][8][HH];
    int tid = threadIdx.x;
    int b0  = blockIdx.x*8;
    #pragma unroll
    for (int r=0;r<8;r++) hs[0][r][tid] = 0.f;
    float bj = bh[tid];
    float ss = 0.f, sq = 0.f;
    __syncthreads();

    const ulonglong2* __restrict__ w = g_Wq + tid;

    int p = 0;
    for (int t=0;t<TT;t++){
        float gk[8], zt[8];
        int off[8];
        #pragma unroll
        for (int r=0;r<8;r++){
            off[r] = ((b0+r)*TT + t)*HH;
            gk[r] = g_xK[off[r]+tid];
            zt[r] = g_z [off[r]+tid];
        }
        ull acc[8];
        #pragma unroll
        for (int r=0;r<8;r++) acc[r] = 0ull;

        const float* hb = &hs[p][0][0];

        ulonglong2 A[4];
        #pragma unroll
        for (int i=0;i<4;i++) A[i] = __ldg(w + i*HH);

        #pragma unroll 1
        for (int kq=0; kq<128; kq+=4){
            int nq = (kq+4) & 127;
            ulonglong2 An[4];
            #pragma unroll
            for (int i=0;i<4;i++) An[i] = __ldg(w + (nq+i)*HH);
            #pragma unroll
            for (int u=0;u<4;u++){
                #pragma unroll
                for (int r=0;r<8;r++){
                    ull h0,h1;
                    lds2(h0,h1, hb + r*HH + 4*(kq+u));
                    fma2(acc[r],h0,A[u].x); fma2(acc[r],h1,A[u].y);
                }
            }
            #pragma unroll
            for (int i=0;i<4;i++) A[i]=An[i];
        }
        #pragma unroll
        for (int r=0;r<8;r++){
            float2 Av = upk2(acc[r]);
            float K  = sigm_f(gk[r] + Av.x + Av.y + bj);
            float hp = hs[p][r][tid];
            float n0 = tanh_f(K*hp + (1.f-K)*zt[r]);
            hs[1-p][r][tid] = n0;
            g_o[off[r]+tid] = n0;
            ss += n0; sq = fmaf(n0,n0,sq);
        }
        __syncthreads();
        p ^= 1;
    }
    g_psum[blockIdx.x*HH + tid] = ss;
    g_psq [blockIdx.x*HH + tid] = sq;
}

// ---------------- 5) finalize BN stats + fold vectors ----------------
__global__ void k_statsfin(const float* __restrict__ bng, const float* __restrict__ bnb){
    int t = threadIdx.x;
    float s = 0.f, q = 0.f;
    for (int i=0;i<NRB;i++){ s += g_psum[i*HH + t]; q += g_psq[i*HH + t]; }
    float m  = s * (1.f/BT);
    float v  = q * (1.f/BT) - m*m;
    float rs = rsqrtf(v + EPSF);
    g_mean[t] = m;
    g_rstd[t] = rs;
    float sc = bng[t]*rs;
    g_s[t] = sc;
    g_c[t] = bnb[t] - m*sc;
}

// ---------------- 6) folded biases: b' = b + W @ c (also writes concat bias) ----------------
__global__ void k_bias(const float* __restrict__ WK, const float* __restrict__ bK,
                       const float* __restrict__ WZ, const float* __restrict__ bZ){
    __shared__ float sk[8], sz[8];
    int j = blockIdx.x, t = threadIdx.x;
    float ck = 0.f, cz = 0.f;
    for (int k=t;k<HH;k+=256){
        float c = g_c[k];
        ck = fmaf(WK[j*HH+k], c, ck);
        cz = fmaf(WZ[j*HH+k], c, cz);
    }
    #pragma unroll
    for (int o=16;o;o>>=1){ ck += __shfl_xor_sync(~0u,ck,o); cz += __shfl_xor_sync(~0u,cz,o); }
    if ((t&31)==0){ sk[t>>5]=ck; sz[t>>5]=cz; }
    __syncthreads();
    if (t==0){
        float a=0.f,b2=0.f;
        #pragma unroll
        for (int i=0;i<8;i++){ a+=sk[i]; b2+=sz[i]; }
        float bk = bK[j] + a;
        float bz = bZ[j] + b2;
        g_bk[j] = bk;  g_bz[j] = bz;
        g_bcat[j] = bk;  g_bcat[512+j] = bz;
    }
}

// ---------------- 6b) pack B for tensor GEMM: tf32-rounded, BN-folded, [k][n] ----------------
__global__ void k_packB(const float* __restrict__ WK, const float* __restrict__ WZ){
    int j = blockIdx.x;       // 512
    int t = threadIdx.x;      // 256
    for (int k=t;k<HH;k+=256){
        float sv = g_s[k];
        uint32_t uk = cvt_tf32(WK[j*HH+k]*sv);
        uint32_t uz = cvt_tf32(WZ[j*HH+k]*sv);
        g_Bt[k*1024 + j]       = __uint_as_float(uk);
        g_Bt[k*1024 + 512 + j] = __uint_as_float(uz);
    }
}

// ---------------- 7) layer-2/3 projections: tf32 tensor GEMM ----------------
// C[BT,1024] = X[BT,512] @ Bt[512,1024];  n<512 -> xK, n>=512 -> z=tanh(.)
__global__ void __launch_bounds__(256,1) k_pmma(){
    extern __shared__ float smem[];
    float* As[2] = { smem, smem + PM*APAD };
    float* Bs[2] = { smem + 2*PM*APAD, smem + 2*PM*APAD + PK*BPAD };
    uint32_t sA[2], sB[2];
    sA[0] = (uint32_t)__cvta_generic_to_shared(As[0]);
    sA[1] = (uint32_t)__cvta_generic_to_shared(As[1]);
    sB[0] = (uint32_t)__cvta_generic_to_shared(Bs[0]);
    sB[1] = (uint32_t)__cvta_generic_to_shared(Bs[1]);

    int tid = threadIdx.x;
    int wid = tid>>5, lane = tid&31;
    int g = lane>>2, tig = lane&3;
    int wm = wid & 1, wn = wid >> 1;
    int m0 = blockIdx.x * PM;
    int nb = blockIdx.y * PN;

    const float* Ag = g_o  + (size_t)m0*HH;
    const float* Bg = g_Bt + nb;

    float acc[4][8][4];
    #pragma unroll
    for (int mt=0;mt<4;mt++)
        #pragma unroll
        for (int nt=0;nt<8;nt++)
            #pragma unroll
            for (int i=0;i<4;i++) acc[mt][nt][i]=0.f;

    auto stage = [&](int c, int buf){
        #pragma unroll
        for (int i=0;i<4;i++){
            int u = i*256 + tid;         // 0..1023
            int row = u>>3, seg = u&7;
            cp16(sA[buf] + (row*APAD + seg*4)*4, Ag + row*HH + c*PK + seg*4);
        }
        #pragma unroll
        for (int i=0;i<8;i++){
            int u = i*256 + tid;         // 0..2047
            int row = u>>6, seg = u&63;
            cp16(sB[buf] + (row*BPAD + seg*4)*4, Bg + (size_t)(c*PK + row)*1024 + seg*4);
        }
        asm volatile("cp.async.commit_group;");
    };

    stage(0, 0);
    #pragma unroll 1
    for (int c=0;c<16;c++){
        int buf = c & 1;
        if (c < 15) stage(c+1, buf^1);
        if (c < 15) asm volatile("cp.async.wait_group 1;");
        else        asm volatile("cp.async.wait_group 0;");
        __syncthreads();

        #pragma unroll
        for (int k8=0;k8<4;k8++){
            int kk = k8*8;
            uint32_t a[4][4];
            #pragma unroll
            for (int mt=0;mt<4;mt++){
                const float* ap = &As[buf][(wm*64 + mt*16 + g)*APAD + kk + tig];
                a[mt][0] = cvt_tf32(ap[0]);
                a[mt][1] = cvt_tf32(ap[8*APAD]);
                a[mt][2] = cvt_tf32(ap[4]);
                a[mt][3] = cvt_tf32(ap[8*APAD+4]);
            }
            uint32_t b[8][2];
            #pragma unroll
            for (int nt=0;nt<8;nt++){
                const float* bp = &Bs[buf][(kk + tig)*BPAD + wn*64 + nt*8 + g];
                b[nt][0] = __float_as_uint(bp[0]);
                b[nt][1] = __float_as_uint(bp[4*BPAD]);
            }
            #pragma unroll
            for (int mt=0;mt<4;mt++)
                #pragma unroll
                for (int nt=0;nt<8;nt++)
                    mma_tf32(acc[mt][nt], a[mt], b[nt]);
        }
        __syncthreads();
    }

    // epilogue
    bool isZ = (nb >= 512);
    #pragma unroll
    for (int mt=0;mt<4;mt++){
        int r0 = m0 + wm*64 + mt*16 + g;
        #pragma unroll
        for (int nt=0;nt<8;nt++){
            int n = nb + wn*64 + nt*8 + 2*tig;
            float b0v = g_bcat[n], b1v = g_bcat[n+1];
            float v00 = acc[mt][nt][0]+b0v, v01 = acc[mt][nt][1]+b1v;
            float v10 = acc[mt][nt][2]+b0v, v11 = acc[mt][nt][3]+b1v;
            if (isZ){
                int nz = n - 512;
                float2 lo = make_float2(tanh_f(v00), tanh_f(v01));
                float2 hi = make_float2(tanh_f(v10), tanh_f(v11));
                *(float2*)&g_z[(size_t)r0*HH + nz]     = lo;
                *(float2*)&g_z[(size_t)(r0+8)*HH + nz] = hi;
            } else {
                *(float2*)&g_xK[(size_t)r0*HH + n]     = make_float2(v00, v01);
                *(float2*)&g_xK[(size_t)(r0+8)*HH + n] = make_float2(v10, v11);
            }
        }
    }
}

// ---------------- 8) head ----------------
__global__ void __launch_bounds__(512) k_head(const float* __restrict__ bng, const float* __restrict__ bnb,
                                              const float* __restrict__ lng, const float* __restrict__ lnb,
                                              const float* __restrict__ Wc,  const float* __restrict__ bc,
                                              float* __restrict__ out){
    __shared__ float red[16];
    __shared__ float hsm[HH];
    __shared__ float lg[CC];
    int b = blockIdx.x, tid = threadIdx.x;

    float v = g_o[(b*TT + TT-1)*HH + tid];
    float y = (v - g_mean[tid])*g_rstd[tid]*bng[tid] + bnb[tid];

    float t1 = y;
    #pragma unroll
    for (int o=16;o;o>>=1) t1 += __shfl_xor_sync(~0u,t1,o);
    if ((tid&31)==0) red[tid>>5] = t1;
    __syncthreads();
    float mu = 0.f;
    #pragma unroll
    for (int i=0;i<16;i++) mu += red[i];
    mu *= (1.f/HH);
    __syncthreads();

    float d = y - mu;
    float t2 = d*d;
    #pragma unroll
    for (int o=16;o;o>>=1) t2 += __shfl_xor_sync(~0u,t2,o);
    if ((tid&31)==0) red[tid>>5] = t2;
    __syncthreads();
    float var = 0.f;
    #pragma unroll
    for (int i=0;i<16;i++) var += red[i];
    var *= (1.f/HH);
    float rs = rsqrtf(var + EPSF);
    hsm[tid] = d*rs*lng[tid] + lnb[tid];
    __syncthreads();

    int w = tid>>5, l = tid&31;
    if (w < CC){
        float p = 0.f;
        for (int k=l;k<HH;k+=32) p = fmaf(hsm[k], Wc[w*HH + k], p);
        #pragma unroll
        for (int o=16;o;o>>=1) p += __shfl_xor_sync(~0u,p,o);
        if (l==0) lg[w] = p + bc[w];
    }
    __syncthreads();
    if (tid==0){
        float mx = lg[0];
        #pragma unroll
        for (int c=1;c<CC;c++) mx = fmaxf(mx, lg[c]);
        float sm = 0.f;
        #pragma unroll
        for (int c=0;c<CC;c++) sm += expf(lg[c]-mx);
        float lse = mx + logf(sm);
        #pragma unroll
        for (int c=0;c<CC;c++) out[b*CC + c] = lg[c] - lse;
    }
}

// ---------------- launch sequence ----------------
extern "C" void kernel_launch(void* const* d_in, const int* in_sizes, int n_in,
                              void* d_out, int out_size){
    const float* x      = (const float*)d_in[0];
    const float* inln_g = (const float*)d_in[1];
    const float* inln_b = (const float*)d_in[2];
    const float* WxK1   = (const float*)d_in[3];
    const float* bxK1   = (const float*)d_in[4];
    const float* Wxz1   = (const float*)d_in[5];
    const float* bxz1   = (const float*)d_in[6];
    const float* WhK1   = (const float*)d_in[7];
    const float* bhK1   = (const float*)d_in[8];
    const float* bn1_g  = (const float*)d_in[9];
    const float* bn1_b  = (const float*)d_in[10];
    const float* WxK2   = (const float*)d_in[11];
    const float* bxK2   = (const float*)d_in[12];
    const float* Wxz2   = (const float*)d_in[13];
    const float* bxz2   = (const float*)d_in[14];
    const float* WhK2   = (const float*)d_in[15];
    const float* bhK2   = (const float*)d_in[16];
    const float* bn2_g  = (const float*)d_in[17];
    const float* bn2_b  = (const float*)d_in[18];
    const float* cln_g  = (const float*)d_in[19];
    const float* cln_b  = (const float*)d_in[20];
    const float* Wc     = (const float*)d_in[21];
    const float* bc     = (const float*)d_in[22];
    float* out = (float*)d_out;

    static int inited = 0;
    if (!inited){
        cudaFuncSetAttribute(k_pmma, cudaFuncAttributeMaxDynamicSharedMemorySize, PMMA_SMEM);
        inited = 1;
    }

    dim3 pg(16,8);
    dim3 mg(BT/PM, 1024/PN);

    // input LN + layer-1 projections
    k_ln   <<<BT/256, 256>>>(x, inln_g, inln_b);
    k_proj1<<<BT/64, 512>>>(WxK1, bxK1, Wxz1, bxz1);

    // layer 1
    k_pack    <<<pg, 256>>>(WhK1);
    k_recur   <<<NRB, 512>>>(bhK1);
    k_statsfin<<<1, 512>>>(bn1_g, bn1_b);
    k_packB   <<<HH, 256>>>(WxK2, Wxz2);
    k_bias    <<<HH, 256>>>(WxK2, bxK2, Wxz2, bxz2);

    // layer 2
    k_pmma    <<<mg, 256, PMMA_SMEM>>>();
    k_pack    <<<pg, 256>>>(WhK2);
    k_recur   <<<NRB, 512>>>(bhK2);
    k_statsfin<<<1, 512>>>(bn2_g, bn2_b);
    k_packB   <<<HH, 256>>>(WxK2, Wxz2);
    k_bias    <<<HH, 256>>>(WxK2, bxK2, Wxz2, bxz2);

    // layer 3 (shared weights; g_Wq still holds packed WhK2)
    k_pmma    <<<mg, 256, PMMA_SMEM>>>();
    k_recur   <<<NRB, 512>>>(bhK2);
    k_statsfin<<<1, 512>>>(bn2_g, bn2_b);

    // head
    k_head <<<BB, 512>>>(bn2_g, bn2_b, cln_g, cln_b, Wc, bc, out);
}

// round 6
// speedup vs baseline: 1.5460x; 1.1269x over previous
#include <cuda_runtime.h>
#include <cstdint>

typedef unsigned long long ull;

#define BB 1024
#define TT 128
#define DD 13
#define HH 512
#define CC 9
#define BT (BB*TT)
#define EPSF 1e-5f
#define NRB 128

#define PM 128
#define PN 256
#define PK 32
#define APAD 36
#define BPAD 260
#define PMMA_SMEM ((2*PM*APAD + 2*PK*BPAD)*4)

// ---------------- scratch (device globals) ----------------
__device__ float g_xn[BT*16];
__device__ float g_xK[BT*HH];
__device__ float g_z [BT*HH];
__device__ float g_o [BT*HH];
__device__ float g_psum[NRB*HH];
__device__ float g_psq [NRB*HH];
__device__ float g_mean[HH], g_rstd[HH], g_s[HH], g_c[HH];
__device__ ulonglong2 g_Wq[128*HH];          // quad-packed transposed recurrence W
__device__ float g_Bt[512*1024];             // tf32-rounded, BN-folded [Wk'|Wz'] as [k][n]
__device__ float g_bcat[1024];

// ---------------- helpers ----------------
__device__ __forceinline__ ull pk2(float x, float y){
    ull r; asm("mov.b64 %0,{%1,%2};" : "=l"(r) : "f"(x), "f"(y)); return r;
}
__device__ __forceinline__ float2 upk2(ull v){
    float2 f; asm("mov.b64 {%0,%1},%2;" : "=f"(f.x), "=f"(f.y) : "l"(v)); return f;
}
__device__ __forceinline__ void fma2(ull &d, ull a, ull b){
    asm("fma.rn.f32x2 %0,%1,%2,%0;" : "+l"(d) : "l"(a), "l"(b));
}
__device__ __forceinline__ void lds2(ull &a, ull &b, const float* p){
    unsigned sa = (unsigned)__cvta_generic_to_shared(p);
    asm volatile("ld.shared.v2.u64 {%0,%1},[%2];" : "=l"(a), "=l"(b) : "r"(sa));
}
__device__ __forceinline__ float sigm_f(float x){
    return __fdividef(1.f, 1.f + __expf(-x));
}
__device__ __forceinline__ float tanh_f(float x){
    return 1.f - 2.f*__fdividef(1.f, __expf(2.f*x) + 1.f);
}
__device__ __forceinline__ uint32_t cvt_tf32(float f){
    uint32_t u; asm("cvt.rna.tf32.f32 %0,%1;" : "=r"(u) : "f"(f)); return u;
}
__device__ __forceinline__ void cp16(uint32_t dst, const void* src){
    asm volatile("cp.async.ca.shared.global [%0],[%1],16;" :: "r"(dst), "l"(src));
}
__device__ __forceinline__ void mma_tf32(float* c, const uint32_t* a, const uint32_t* b){
    asm volatile("mma.sync.aligned.m16n8k8.row.col.f32.tf32.tf32.f32 "
        "{%0,%1,%2,%3},{%4,%5,%6,%7},{%8,%9},{%0,%1,%2,%3};"
        : "+f"(c[0]), "+f"(c[1]), "+f"(c[2]), "+f"(c[3])
        : "r"(a[0]), "r"(a[1]), "r"(a[2]), "r"(a[3]), "r"(b[0]), "r"(b[1]));
}

// ---------------- 1) input LayerNorm over D=13 ----------------
__global__ void k_ln(const float* __restrict__ x, const float* __restrict__ g,
                     const float* __restrict__ b){
    int m = blockIdx.x*blockDim.x + threadIdx.x;
    if (m >= BT) return;
    const float* r = x + m*DD;
    float s = 0.f;
    #pragma unroll
    for (int k=0;k<DD;k++) s += r[k];
    float mu = s * (1.f/DD);
    float v = 0.f;
    #pragma unroll
    for (int k=0;k<DD;k++){ float d = r[k]-mu; v += d*d; }
    float rs = rsqrtf(v*(1.f/DD) + EPSF);
    float* o = g_xn + m*16;
    #pragma unroll
    for (int k=0;k<DD;k++) o[k] = (r[k]-mu)*rs*g[k] + b[k];
    o[13]=0.f; o[14]=0.f; o[15]=0.f;
}

// ---------------- 2) layer-1 projections (K=13) ----------------
__global__ void __launch_bounds__(512) k_proj1(const float* __restrict__ WK, const float* __restrict__ bK,
                                               const float* __restrict__ WZ, const float* __restrict__ bZ){
    __shared__ float xt[64][16];
    int tid = threadIdx.x;
    int m0  = blockIdx.x*64;
    #pragma unroll
    for (int i=0;i<2;i++){
        int idx = tid + i*512;
        xt[idx>>4][idx&15] = g_xn[m0*16 + idx];
    }
    float wk[DD], wz[DD];
    #pragma unroll
    for (int i=0;i<DD;i++){ wk[i]=WK[tid*DD+i]; wz[i]=WZ[tid*DD+i]; }
    float bk = bK[tid], bz = bZ[tid];
    __syncthreads();
    for (int m=0;m<64;m++){
        float ak = bk, az = bz;
        #pragma unroll
        for (int i=0;i<DD;i++){ float xv = xt[m][i]; ak = fmaf(xv,wk[i],ak); az = fmaf(xv,wz[i],az); }
        g_xK[(m0+m)*HH + tid] = ak;
        g_z [(m0+m)*HH + tid] = tanh_f(az);
    }
}

// ---------------- 3) pack recurrence W: [j][k] -> quad-packed transposed [k/4][j] ----------------
__global__ void k_pack(const float* __restrict__ src){
    __shared__ float ts[32][65];
    int t  = threadIdx.x;            // 256 threads
    int j0 = blockIdx.x*32;
    int k0 = blockIdx.y*64;
    #pragma unroll
    for (int it=0; it<8; it++){
        int idx = it*256 + t;
        int jj = idx >> 6, kk = idx & 63;
        ts[jj][kk] = src[(j0+jj)*HH + k0 + kk];
    }
    __syncthreads();
    #pragma unroll
    for (int it=0; it<2; it++){
        int idx = it*256 + t;
        int jj = idx & 31, kql = idx >> 5;
        ulonglong2 o;
        o.x = pk2(ts[jj][4*kql  ], ts[jj][4*kql+1]);
        o.y = pk2(ts[jj][4*kql+2], ts[jj][4*kql+3]);
        g_Wq[(k0/4 + kql)*HH + j0 + jj] = o;
    }
}

// ---------------- 4) recurrence: 256 thr, 2 outs/thread, prefetch, stream hints ----------------
__global__ void __launch_bounds__(256,1) k_recur(const float* __restrict__ bh){
    __shared__ __align__(16) float hs[2][8][HH];
    int tid = threadIdx.x;
    int j1  = tid + 256;
    int b0  = blockIdx.x*8;
    #pragma unroll
    for (int r=0;r<8;r++){ hs[0][r][tid]=0.f; hs[0][r][j1]=0.f; }
    float bj0 = bh[tid], bj1 = bh[j1];
    float ss0=0.f, sq0=0.f, ss1=0.f, sq1=0.f;
    __syncthreads();

    const ulonglong2* __restrict__ w0 = g_Wq + tid;
    const ulonglong2* __restrict__ w1 = g_Wq + j1;

    int p = 0;
    for (int t=0;t<TT;t++){
        float gk0[8], zt0[8], gk1[8], zt1[8];
        int off[8];
        #pragma unroll
        for (int r=0;r<8;r++){
            off[r] = ((b0+r)*TT + t)*HH;
            gk0[r] = __ldcs(&g_xK[off[r]+tid]);
            zt0[r] = __ldcs(&g_z [off[r]+tid]);
            gk1[r] = __ldcs(&g_xK[off[r]+j1]);
            zt1[r] = __ldcs(&g_z [off[r]+j1]);
        }
        ull a0[8], a1[8];
        #pragma unroll
        for (int r=0;r<8;r++){ a0[r]=0ull; a1[r]=0ull; }

        const float* hb = &hs[p][0][0];

        // software pipeline: prefetch distance = 4 kq
        ulonglong2 A[4], B[4];
        #pragma unroll
        for (int i=0;i<4;i++){ A[i] = __ldg(w0 + i*HH); B[i] = __ldg(w1 + i*HH); }

        #pragma unroll 1
        for (int kq=0; kq<128; kq+=4){
            int nq = (kq+4) & 127;
            ulonglong2 An[4], Bn[4];
            #pragma unroll
            for (int i=0;i<4;i++){ An[i] = __ldg(w0 + (nq+i)*HH); Bn[i] = __ldg(w1 + (nq+i)*HH); }
            #pragma unroll
            for (int u=0;u<4;u++){
                #pragma unroll
                for (int r=0;r<8;r++){
                    ull h0,h1;
                    lds2(h0,h1, hb + r*HH + 4*(kq+u));
                    fma2(a0[r],h0,A[u].x); fma2(a0[r],h1,A[u].y);
                    fma2(a1[r],h0,B[u].x); fma2(a1[r],h1,B[u].y);
                }
            }
            #pragma unroll
            for (int i=0;i<4;i++){ A[i]=An[i]; B[i]=Bn[i]; }
        }
        #pragma unroll
        for (int r=0;r<8;r++){
            float2 Av = upk2(a0[r]);
            float2 Bv = upk2(a1[r]);
            float K0 = sigm_f(gk0[r] + Av.x + Av.y + bj0);
            float K1 = sigm_f(gk1[r] + Bv.x + Bv.y + bj1);
            float h00 = hs[p][r][tid], h01 = hs[p][r][j1];
            float n0 = tanh_f(K0*h00 + (1.f-K0)*zt0[r]);
            float n1 = tanh_f(K1*h01 + (1.f-K1)*zt1[r]);
            hs[1-p][r][tid] = n0;
            hs[1-p][r][j1]  = n1;
            __stcs(&g_o[off[r]+tid], n0);
            __stcs(&g_o[off[r]+j1 ], n1);
            ss0 += n0; sq0 = fmaf(n0,n0,sq0);
            ss1 += n1; sq1 = fmaf(n1,n1,sq1);
        }
        __syncthreads();
        p ^= 1;
    }
    g_psum[blockIdx.x*HH + tid] = ss0;
    g_psum[blockIdx.x*HH + j1 ] = ss1;
    g_psq [blockIdx.x*HH + tid] = sq0;
    g_psq [blockIdx.x*HH + j1 ] = sq1;
}

// ---------------- 5) finalize BN stats + fold vectors ----------------
__global__ void k_statsfin(const float* __restrict__ bng, const float* __restrict__ bnb){
    int t = threadIdx.x;
    float s = 0.f, q = 0.f;
    for (int i=0;i<NRB;i++){ s += g_psum[i*HH + t]; q += g_psq[i*HH + t]; }
    float m  = s * (1.f/BT);
    float v  = q * (1.f/BT) - m*m;
    float rs = rsqrtf(v + EPSF);
    g_mean[t] = m;
    g_rstd[t] = rs;
    float sc = bng[t]*rs;
    g_s[t] = sc;
    g_c[t] = bnb[t] - m*sc;
}

// ---------------- 6) fold: biases + tf32 B pack in one kernel ----------------
__global__ void k_fold2(const float* __restrict__ WK, const float* __restrict__ bK,
                        const float* __restrict__ WZ, const float* __restrict__ bZ){
    __shared__ float sk[8], sz[8];
    int j = blockIdx.x, t = threadIdx.x;   // 512 blocks x 256 threads
    float ck = 0.f, cz = 0.f;
    for (int k=t;k<HH;k+=256){
        float wkv = WK[j*HH+k];
        float wzv = WZ[j*HH+k];
        float c = g_c[k];
        float sv = g_s[k];
        ck = fmaf(wkv, c, ck);
        cz = fmaf(wzv, c, cz);
        g_Bt[k*1024 + j]       = __uint_as_float(cvt_tf32(wkv*sv));
        g_Bt[k*1024 + 512 + j] = __uint_as_float(cvt_tf32(wzv*sv));
    }
    #pragma unroll
    for (int o=16;o;o>>=1){ ck += __shfl_xor_sync(~0u,ck,o); cz += __shfl_xor_sync(~0u,cz,o); }
    if ((t&31)==0){ sk[t>>5]=ck; sz[t>>5]=cz; }
    __syncthreads();
    if (t==0){
        float a=0.f,b2=0.f;
        #pragma unroll
        for (int i=0;i<8;i++){ a+=sk[i]; b2+=sz[i]; }
        g_bcat[j]     = bK[j] + a;
        g_bcat[512+j] = bZ[j] + b2;
    }
}

// ---------------- 7) layer-2/3 projections: tf32 tensor GEMM ----------------
__global__ void __launch_bounds__(256,1) k_pmma(){
    extern __shared__ float smem[];
    float* As[2] = { smem, smem + PM*APAD };
    float* Bs[2] = { smem + 2*PM*APAD, smem + 2*PM*APAD + PK*BPAD };
    uint32_t sA[2], sB[2];
    sA[0] = (uint32_t)__cvta_generic_to_shared(As[0]);
    sA[1] = (uint32_t)__cvta_generic_to_shared(As[1]);
    sB[0] = (uint32_t)__cvta_generic_to_shared(Bs[0]);
    sB[1] = (uint32_t)__cvta_generic_to_shared(Bs[1]);

    int tid = threadIdx.x;
    int wid = tid>>5, lane = tid&31;
    int g = lane>>2, tig = lane&3;
    int wm = wid & 1, wn = wid >> 1;
    int m0 = blockIdx.x * PM;
    int nb = blockIdx.y * PN;

    const float* Ag = g_o  + (size_t)m0*HH;
    const float* Bg = g_Bt + nb;

    float acc[4][8][4];
    #pragma unroll
    for (int mt=0;mt<4;mt++)
        #pragma unroll
        for (int nt=0;nt<8;nt++)
            #pragma unroll
            for (int i=0;i<4;i++) acc[mt][nt][i]=0.f;

    auto stage = [&](int c, int buf){
        #pragma unroll
        for (int i=0;i<4;i++){
            int u = i*256 + tid;
            int row = u>>3, seg = u&7;
            cp16(sA[buf] + (row*APAD + seg*4)*4, Ag + row*HH + c*PK + seg*4);
        }
        #pragma unroll
        for (int i=0;i<8;i++){
            int u = i*256 + tid;
            int row = u>>6, seg = u&63;
            cp16(sB[buf] + (row*BPAD + seg*4)*4, Bg + (size_t)(c*PK + row)*1024 + seg*4);
        }
        asm volatile("cp.async.commit_group;");
    };

    stage(0, 0);
    #pragma unroll 1
    for (int c=0;c<16;c++){
        int buf = c & 1;
        if (c < 15) stage(c+1, buf^1);
        if (c < 15) asm volatile("cp.async.wait_group 1;");
        else        asm volatile("cp.async.wait_group 0;");
        __syncthreads();

        #pragma unroll
        for (int k8=0;k8<4;k8++){
            int kk = k8*8;
            uint32_t a[4][4];
            #pragma unroll
            for (int mt=0;mt<4;mt++){
                const float* ap = &As[buf][(wm*64 + mt*16 + g)*APAD + kk + tig];
                a[mt][0] = cvt_tf32(ap[0]);
                a[mt][1] = cvt_tf32(ap[8*APAD]);
                a[mt][2] = cvt_tf32(ap[4]);
                a[mt][3] = cvt_tf32(ap[8*APAD+4]);
            }
            uint32_t b[8][2];
            #pragma unroll
            for (int nt=0;nt<8;nt++){
                const float* bp = &Bs[buf][(kk + tig)*BPAD + wn*64 + nt*8 + g];
                b[nt][0] = __float_as_uint(bp[0]);
                b[nt][1] = __float_as_uint(bp[4*BPAD]);
            }
            #pragma unroll
            for (int mt=0;mt<4;mt++)
                #pragma unroll
                for (int nt=0;nt<8;nt++)
                    mma_tf32(acc[mt][nt], a[mt], b[nt]);
        }
        __syncthreads();
    }

    bool isZ = (nb >= 512);
    #pragma unroll
    for (int mt=0;mt<4;mt++){
        int r0 = m0 + wm*64 + mt*16 + g;
        #pragma unroll
        for (int nt=0;nt<8;nt++){
            int n = nb + wn*64 + nt*8 + 2*tig;
            float b0v = g_bcat[n], b1v = g_bcat[n+1];
            float v00 = acc[mt][nt][0]+b0v, v01 = acc[mt][nt][1]+b1v;
            float v10 = acc[mt][nt][2]+b0v, v11 = acc[mt][nt][3]+b1v;
            if (isZ){
                int nz = n - 512;
                float2 lo = make_float2(tanh_f(v00), tanh_f(v01));
                float2 hi = make_float2(tanh_f(v10), tanh_f(v11));
                *(float2*)&g_z[(size_t)r0*HH + nz]     = lo;
                *(float2*)&g_z[(size_t)(r0+8)*HH + nz] = hi;
            } else {
                *(float2*)&g_xK[(size_t)r0*HH + n]     = make_float2(v00, v01);
                *(float2*)&g_xK[(size_t)(r0+8)*HH + n] = make_float2(v10, v11);
            }
        }
    }
}

// ---------------- 8) head ----------------
__global__ void __launch_bounds__(512) k_head(const float* __restrict__ bng, const float* __restrict__ bnb,
                                              const float* __restrict__ lng, const float* __restrict__ lnb,
                                              const float* __restrict__ Wc,  const float* __restrict__ bc,
                                              float* __restrict__ out){
    __shared__ float red[16];
    __shared__ float hsm[HH];
    __shared__ float lg[CC];
    int b = blockIdx.x, tid = threadIdx.x;

    float v = g_o[(b*TT + TT-1)*HH + tid];
    float y = (v - g_mean[tid])*g_rstd[tid]*bng[tid] + bnb[tid];

    float t1 = y;
    #pragma unroll
    for (int o=16;o;o>>=1) t1 += __shfl_xor_sync(~0u,t1,o);
    if ((tid&31)==0) red[tid>>5] = t1;
    __syncthreads();
    float mu = 0.f;
    #pragma unroll
    for (int i=0;i<16;i++) mu += red[i];
    mu *= (1.f/HH);
    __syncthreads();

    float d = y - mu;
    float t2 = d*d;
    #pragma unroll
    for (int o=16;o;o>>=1) t2 += __shfl_xor_sync(~0u,t2,o);
    if ((tid&31)==0) red[tid>>5] = t2;
    __syncthreads();
    float var = 0.f;
    #pragma unroll
    for (int i=0;i<16;i++) var += red[i];
    var *= (1.f/HH);
    float rs = rsqrtf(var + EPSF);
    hsm[tid] = d*rs*lng[tid] + lnb[tid];
    __syncthreads();

    int w = tid>>5, l = tid&31;
    if (w < CC){
        float p = 0.f;
        for (int k=l;k<HH;k+=32) p = fmaf(hsm[k], Wc[w*HH + k], p);
        #pragma unroll
        for (int o=16;o;o>>=1) p += __shfl_xor_sync(~0u,p,o);
        if (l==0) lg[w] = p + bc[w];
    }
    __syncthreads();
    if (tid==0){
        float mx = lg[0];
        #pragma unroll
        for (int c=1;c<CC;c++) mx = fmaxf(mx, lg[c]);
        float sm = 0.f;
        #pragma unroll
        for (int c=0;c<CC;c++) sm += expf(lg[c]-mx);
        float lse = mx + logf(sm);
        #pragma unroll
        for (int c=0;c<CC;c++) out[b*CC + c] = lg[c] - lse;
    }
}

// ---------------- launch sequence ----------------
extern "C" void kernel_launch(void* const* d_in, const int* in_sizes, int n_in,
                              void* d_out, int out_size){
    const float* x      = (const float*)d_in[0];
    const float* inln_g = (const float*)d_in[1];
    const float* inln_b = (const float*)d_in[2];
    const float* WxK1   = (const float*)d_in[3];
    const float* bxK1   = (const float*)d_in[4];
    const float* Wxz1   = (const float*)d_in[5];
    const float* bxz1   = (const float*)d_in[6];
    const float* WhK1   = (const float*)d_in[7];
    const float* bhK1   = (const float*)d_in[8];
    const float* bn1_g  = (const float*)d_in[9];
    const float* bn1_b  = (const float*)d_in[10];
    const float* WxK2   = (const float*)d_in[11];
    const float* bxK2   = (const float*)d_in[12];
    const float* Wxz2   = (const float*)d_in[13];
    const float* bxz2   = (const float*)d_in[14];
    const float* WhK2   = (const float*)d_in[15];
    const float* bhK2   = (const float*)d_in[16];
    const float* bn2_g  = (const float*)d_in[17];
    const float* bn2_b  = (const float*)d_in[18];
    const float* cln_g  = (const float*)d_in[19];
    const float* cln_b  = (const float*)d_in[20];
    const float* Wc     = (const float*)d_in[21];
    const float* bc     = (const float*)d_in[22];
    float* out = (float*)d_out;

    static int inited = 0;
    if (!inited){
        cudaFuncSetAttribute(k_pmma, cudaFuncAttributeMaxDynamicSharedMemorySize, PMMA_SMEM);
        inited = 1;
    }

    dim3 pg(16,8);
    dim3 mg(BT/PM, 1024/PN);

    // input LN + layer-1 projections
    k_ln   <<<BT/256, 256>>>(x, inln_g, inln_b);
    k_proj1<<<BT/64, 512>>>(WxK1, bxK1, Wxz1, bxz1);

    // layer 1
    k_pack    <<<pg, 256>>>(WhK1);
    k_recur   <<<NRB, 256>>>(bhK1);
    k_statsfin<<<1, 512>>>(bn1_g, bn1_b);
    k_fold2   <<<HH, 256>>>(WxK2, bxK2, Wxz2, bxz2);

    // layer 2
    k_pmma    <<<mg, 256, PMMA_SMEM>>>();
    k_pack    <<<pg, 256>>>(WhK2);
    k_recur   <<<NRB, 256>>>(bhK2);
    k_statsfin<<<1, 512>>>(bn2_g, bn2_b);
    k_fold2   <<<HH, 256>>>(WxK2, bxK2, Wxz2, bxz2);

    // layer 3 (shared weights; g_Wq still holds packed WhK2)
    k_pmma    <<<mg, 256, PMMA_SMEM>>>();
    k_recur   <<<NRB, 256>>>(bhK2);
    k_statsfin<<<1, 512>>>(bn2_g, bn2_b);

    // head
    k_head <<<BB, 512>>>(bn2_g, bn2_b, cln_g, cln_b, Wc, bc, out);
}